// round 5
// baseline (speedup 1.0000x reference)
#include <cuda_runtime.h>
#include <math.h>

// Problem constants
#define BB   2
#define AA   3
#define NCLS 3
#define CC   (NCLS*AA)   // 9 channels
#define DD   64
#define HH   128
#define WW   128
#define MM   128
#define EPSF 1e-4f

#define HT     16                // output rows per block tile
#define DSPLIT 2
#define DCHUNK (DD/DSPLIT)       // 32 d-slices per block
#define TYN    (HT + 2)          // 18 rows incl. halo
#define NWARP  TYN               // one warp per row (32 lanes x float4 = 128 w)

#define NEG_BLOCKS (BB * CC * (HH/HT) * DSPLIT)   // 288

#define NEG_INF __int_as_float(0xff800000)

__device__ __forceinline__ float warp_sum(float v) {
    #pragma unroll
    for (int o = 16; o; o >>= 1) v += __shfl_down_sync(0xffffffffu, v, o);
    return v;
}

__device__ __forceinline__ float4 fmax4(float4 a, float4 b) {
    return make_float4(fmaxf(a.x, b.x), fmaxf(a.y, b.y),
                       fmaxf(a.z, b.z), fmaxf(a.w, b.w));
}

// w-direction 3-window max of a row held as float4 per lane (warp-wide row).
__device__ __forceinline__ float4 wmax3(float4 v, int lane) {
    float left  = __shfl_up_sync(0xffffffffu, v.w, 1);
    float right = __shfl_down_sync(0xffffffffu, v.x, 1);
    if (lane == 0)  left  = NEG_INF;
    if (lane == 31) right = NEG_INF;
    float4 r;
    r.x = fmaxf(fmaxf(left, v.x), v.y);
    r.y = fmaxf(fmaxf(v.x, v.y), v.z);
    r.z = fmaxf(fmaxf(v.y, v.z), v.w);
    r.w = fmaxf(fmaxf(v.z, v.w), right);
    return r;
}

__global__ __launch_bounds__(32 * TYN, 2)
void focal_kernel(const float* __restrict__ logits,
                  const float* __restrict__ prob_gt,
                  const int* __restrict__ coord,
                  const float* __restrict__ wcls,
                  float* __restrict__ out)
{
    __shared__ float4 rbuf[2][TYN][32];       // per-plane row-wmax, double-buffered
    __shared__ float  redl[NWARP], redc[NWARP];

    const int lane = threadIdx.x;             // 0..31 (w4)
    const int ty   = threadIdx.y;             // 0..17
    const int tid  = ty * 32 + lane;
    const int gid  = blockIdx.x;

    // ======================= POS / OTHER path (one block) ===================
    if (gid == NEG_BLOCKS) {
        __shared__ int   present[BB][NCLS];
        __shared__ float rp0[NWARP], rp1[NWARP], rp2[NWARP], rp3[NWARP];

        if (tid < BB * NCLS) present[tid / NCLS][tid % NCLS] = 0;
        __syncthreads();

        const bool active = tid < BB * MM;    // 256 threads do work
        const int b = tid >> 7;
        const int m = tid & (MM - 1);

        float lpos = 0.f, cpos = 0.f, loth = 0.f, coth = 0.f;
        int cls = 0, a = 0, d = 0, h = 0, w = 0;
        bool valid = false;
        if (active) {
            const int* cg = coord + ((size_t)b * MM + m) * 4;
            const int c0 = cg[0];
            valid = c0 > -1;
            a = valid ? c0    : 0;
            d = valid ? cg[1] : 0;
            h = valid ? cg[2] : 0;
            w = valid ? cg[3] : 0;
            const float pgv = prob_gt[(((size_t)(b * AA + a) * DD + d) * HH + h) * WW + w];
            cls = valid ? ((int)pgv - 1) : 0;
            cls = min(max(cls, 0), NCLS - 1);
            if (valid) present[b][cls] = 1;   // benign race
        }
        __syncthreads();

        if (active) {
            const float vf = valid ? 1.0f : 0.0f;
            auto getp = [&](int ch) -> float {
                const float x = logits[(((size_t)(b * CC + ch) * DD + d) * HH + h) * WW + w];
                float p = 1.0f / (1.0f + expf(-x));
                return fminf(fmaxf(p, EPSF), 1.0f - EPSF);
            };
            const float pt   = getp(cls * AA + a);
            const float omt  = 1.0f - pt;
            const float wpos = omt * omt * wcls[cls] * vf;
            lpos = -logf(pt) * wpos;
            cpos = wpos;

            const float thr = pt - 0.1f;
            const float ptgate = (pt > 0.5f) ? 1.0f : 0.0f;
            #pragma unroll
            for (int k = 0; k < NCLS; ++k) {
                const float po = getp(k * AA + a);
                float wo = fmaxf(po - thr, 0.0f);
                wo *= (po > 0.5f) ? 1.0f : 0.0f;
                wo *= ptgate;
                if (present[b][k]) wo = 0.0f;
                wo *= vf;
                loth += -logf(1.0f - po) * wo;
                coth += wo;
            }
        }

        const int wid = tid >> 5, ln = tid & 31;
        lpos = warp_sum(lpos); cpos = warp_sum(cpos);
        loth = warp_sum(loth); coth = warp_sum(coth);
        if (ln == 0) { rp0[wid] = lpos; rp1[wid] = cpos; rp2[wid] = loth; rp3[wid] = coth; }
        __syncthreads();
        if (tid == 0) {
            float s0 = 0, s1 = 0, s2 = 0, s3 = 0;
            #pragma unroll
            for (int i = 0; i < NWARP; ++i) { s0 += rp0[i]; s1 += rp1[i]; s2 += rp2[i]; s3 += rp3[i]; }
            atomicAdd(&out[0], s0);   // l_pos
            atomicAdd(&out[3], s1);   // c_pos
            atomicAdd(&out[2], s2);   // l_oth
            atomicAdd(&out[5], s3);   // c_oth
        }
        return;
    }

    // ============================ NEG path ==================================
    // gid in [0, 288): bc = gid>>4 (channel pair), t = gid&15 -> (h tile, d half)
    const int bc = gid >> 4;              // 0..17
    const int t  = gid & 15;
    const int b  = bc / CC;
    const int c  = bc % CC;
    const int a  = c % AA;                // negmask uses prob_gt[b, a]
    const int h0 = (t & 7) * HT;
    const int d0 = (t >> 3) * DCHUNK;

    const int  h    = h0 - 1 + ty;        // -1..128
    const bool hin  = (h >= 0) && (h < HH);
    const bool isout = (ty >= 1) && (ty <= HT);   // h in [h0, h0+15], always in range

    const float* chan = logits  + (size_t)(b * CC + c) * DD * HH * WW;
    const float* pga  = prob_gt + (size_t)(b * AA + a) * DD * HH * WW;
    const float* rowp = chan + (size_t)h * WW + lane * 4;   // valid iff hin
    const float* pgp  = pga  + (size_t)h * WW + lane * 4;   // valid iff isout

    const float4 ninf4 = make_float4(NEG_INF, NEG_INF, NEG_INF, NEG_INF);

    auto load_plane = [&](int pd) -> float4 {
        if (hin && pd >= 0 && pd < DD)
            return *(const float4*)(rowp + (size_t)pd * HH * WW);
        return ninf4;
    };

    float4 vcur, hm_m1, hm_0;

    // ---- prologue: plane d0-1 ----
    {
        float4 v = load_plane(d0 - 1);
        rbuf[(d0 - 1) & 1][ty][lane] = wmax3(v, lane);
        __syncthreads();
        if (isout) {
            const int par = (d0 - 1) & 1;
            hm_m1 = fmax4(fmax4(rbuf[par][ty - 1][lane], rbuf[par][ty][lane]),
                          rbuf[par][ty + 1][lane]);
        }
    }
    // ---- prologue: plane d0 ----
    {
        vcur = load_plane(d0);
        rbuf[d0 & 1][ty][lane] = wmax3(vcur, lane);
        __syncthreads();
        if (isout) {
            const int par = d0 & 1;
            hm_0 = fmax4(fmax4(rbuf[par][ty - 1][lane], rbuf[par][ty][lane]),
                         rbuf[par][ty + 1][lane]);
        }
    }

    float loss = 0.0f, cnt = 0.0f;
    int par = (d0 + 1) & 1;               // parity of plane d+1 in first iter

    for (int d = d0; d < d0 + DCHUNK; ++d) {
        // prefetch prob_gt for current d (consumed after barrier)
        float4 pg = ninf4;
        if (isout) pg = *(const float4*)(pgp + (size_t)d * HH * WW);

        // pipeline: load plane d+1, publish its row-wmax
        float4 vnext = load_plane(d + 1);
        rbuf[par][ty][lane] = wmax3(vnext, lane);
        __syncthreads();

        if (isout) {
            float4 hm_p1 = fmax4(fmax4(rbuf[par][ty - 1][lane], rbuf[par][ty][lane]),
                                 rbuf[par][ty + 1][lane]);
            float4 m = fmax4(fmax4(hm_m1, hm_0), hm_p1);

            // per-component focal negative loss
            {
                const float mm[4]  = { m.x, m.y, m.z, m.w };
                const float cc4[4] = { vcur.x, vcur.y, vcur.z, vcur.w };
                const float pp[4]  = { pg.x, pg.y, pg.z, pg.w };
                #pragma unroll
                for (int i = 0; i < 4; ++i) {
                    if (mm[i] == cc4[i] && pp[i] == -1.0f) {
                        float p = 1.0f / (1.0f + expf(-cc4[i]));
                        p = fminf(fmaxf(p, EPSF), 1.0f - EPSF);
                        if (p > EPSF) {
                            const float w = p * p;      // p^ALPHA, ALPHA=2
                            loss -= logf(1.0f - p) * w;
                            cnt  += w;
                        }
                    }
                }
            }
            hm_m1 = hm_0;
            hm_0  = hm_p1;
        }
        vcur = vnext;
        par ^= 1;
    }

    // block reduction (18 warps; warp == one ty row)
    loss = warp_sum(loss);
    cnt  = warp_sum(cnt);
    if (lane == 0) { redl[ty] = loss; redc[ty] = cnt; }
    __syncthreads();
    if (tid == 0) {
        float l = 0.f, cv = 0.f;
        #pragma unroll
        for (int i = 0; i < NWARP; ++i) { l += redl[i]; cv += redc[i]; }
        atomicAdd(&out[1], l);    // loss_neg
        atomicAdd(&out[4], cv);   // count_neg
    }
}

extern "C" void kernel_launch(void* const* d_in, const int* in_sizes, int n_in,
                              void* d_out, int out_size)
{
    const float* logits  = (const float*)d_in[0];
    const float* prob_gt = (const float*)d_in[1];
    const int*   coord   = (const int*)d_in[2];
    const float* wcls    = (const float*)d_in[3];
    float* out = (float*)d_out;

    cudaMemsetAsync(out, 0, (size_t)out_size * sizeof(float));

    // 1D grid: 288 neg work blocks + 1 pos block = 289 <= 296 resident CTAs
    focal_kernel<<<NEG_BLOCKS + 1, dim3(32, TYN)>>>(logits, prob_gt, coord, wcls, out);
}

// round 7
// speedup vs baseline: 1.0859x; 1.0859x over previous
#include <cuda_runtime.h>
#include <math.h>

// Problem constants
#define BB   2
#define AA   3
#define NCLS 3
#define CC   (NCLS*AA)   // 9 channels
#define DD   64
#define HH   128
#define WW   128
#define MM   128
#define EPSF 1e-4f

#define HT     16                // output rows per block tile
#define DSPLIT 2
#define DCHUNK (DD/DSPLIT)       // 32 d-slices per block
#define TYN    (HT + 2)          // 18 rows incl. halo
#define NWARP  TYN               // one warp per row (32 lanes x float4 = 128 w)

#define NEG_BLOCKS (BB * CC * (HH/HT) * DSPLIT)   // 288

#define NEG_INF __int_as_float(0xff800000)

__device__ __forceinline__ float warp_sum(float v) {
    #pragma unroll
    for (int o = 16; o; o >>= 1) v += __shfl_down_sync(0xffffffffu, v, o);
    return v;
}

__device__ __forceinline__ float4 fmax4(float4 a, float4 b) {
    return make_float4(fmaxf(a.x, b.x), fmaxf(a.y, b.y),
                       fmaxf(a.z, b.z), fmaxf(a.w, b.w));
}

// w-direction 3-window max of a row held as float4 per lane (warp-wide row).
__device__ __forceinline__ float4 wmax3(float4 v, int lane) {
    float left  = __shfl_up_sync(0xffffffffu, v.w, 1);
    float right = __shfl_down_sync(0xffffffffu, v.x, 1);
    if (lane == 0)  left  = NEG_INF;
    if (lane == 31) right = NEG_INF;
    float4 r;
    r.x = fmaxf(fmaxf(left, v.x), v.y);
    r.y = fmaxf(fmaxf(v.x, v.y), v.z);
    r.z = fmaxf(fmaxf(v.y, v.z), v.w);
    r.w = fmaxf(fmaxf(v.z, v.w), right);
    return r;
}

__global__ __launch_bounds__(32 * TYN, 2)
void focal_kernel(const float* __restrict__ logits,
                  const float* __restrict__ prob_gt,
                  const int* __restrict__ coord,
                  const float* __restrict__ wcls,
                  float* __restrict__ out)
{
    __shared__ float4 rbuf[4][TYN][32];       // 4-slot ring of per-plane row-wmax
    __shared__ float  redl[NWARP], redc[NWARP];

    const int lane = threadIdx.x;             // 0..31 (w4)
    const int ty   = threadIdx.y;             // 0..17
    const int tid  = ty * 32 + lane;
    const int gid  = blockIdx.x;

    // ======================= POS / OTHER path (one block) ===================
    if (gid == NEG_BLOCKS) {
        __shared__ int   present[BB][NCLS];
        __shared__ float rp0[NWARP], rp1[NWARP], rp2[NWARP], rp3[NWARP];

        if (tid < BB * NCLS) present[tid / NCLS][tid % NCLS] = 0;
        __syncthreads();

        const bool active = tid < BB * MM;    // 256 threads do work
        const int b = tid >> 7;
        const int m = tid & (MM - 1);

        float lpos = 0.f, cpos = 0.f, loth = 0.f, coth = 0.f;
        int cls = 0, a = 0, d = 0, h = 0, w = 0;
        bool valid = false;
        if (active) {
            const int* cg = coord + ((size_t)b * MM + m) * 4;
            const int c0 = cg[0];
            valid = c0 > -1;
            a = valid ? c0    : 0;
            d = valid ? cg[1] : 0;
            h = valid ? cg[2] : 0;
            w = valid ? cg[3] : 0;
            const float pgv = prob_gt[(((size_t)(b * AA + a) * DD + d) * HH + h) * WW + w];
            cls = valid ? ((int)pgv - 1) : 0;
            cls = min(max(cls, 0), NCLS - 1);
            if (valid) present[b][cls] = 1;   // benign race
        }
        __syncthreads();

        if (active) {
            const float vf = valid ? 1.0f : 0.0f;
            auto getp = [&](int ch) -> float {
                const float x = logits[(((size_t)(b * CC + ch) * DD + d) * HH + h) * WW + w];
                float p = 1.0f / (1.0f + expf(-x));
                return fminf(fmaxf(p, EPSF), 1.0f - EPSF);
            };
            const float pt   = getp(cls * AA + a);
            const float omt  = 1.0f - pt;
            const float wpos = omt * omt * wcls[cls] * vf;
            lpos = -logf(pt) * wpos;
            cpos = wpos;

            const float thr = pt - 0.1f;
            const float ptgate = (pt > 0.5f) ? 1.0f : 0.0f;
            #pragma unroll
            for (int k = 0; k < NCLS; ++k) {
                const float po = getp(k * AA + a);
                float wo = fmaxf(po - thr, 0.0f);
                wo *= (po > 0.5f) ? 1.0f : 0.0f;
                wo *= ptgate;
                if (present[b][k]) wo = 0.0f;
                wo *= vf;
                loth += -logf(1.0f - po) * wo;
                coth += wo;
            }
        }

        const int wid = tid >> 5, ln = tid & 31;
        lpos = warp_sum(lpos); cpos = warp_sum(cpos);
        loth = warp_sum(loth); coth = warp_sum(coth);
        if (ln == 0) { rp0[wid] = lpos; rp1[wid] = cpos; rp2[wid] = loth; rp3[wid] = coth; }
        __syncthreads();
        if (tid == 0) {
            float s0 = 0, s1 = 0, s2 = 0, s3 = 0;
            #pragma unroll
            for (int i = 0; i < NWARP; ++i) { s0 += rp0[i]; s1 += rp1[i]; s2 += rp2[i]; s3 += rp3[i]; }
            atomicAdd(&out[0], s0);   // l_pos
            atomicAdd(&out[3], s1);   // c_pos
            atomicAdd(&out[2], s2);   // l_oth
            atomicAdd(&out[5], s3);   // c_oth
        }
        return;
    }

    // ============================ NEG path ==================================
    const int bc = gid >> 4;              // 0..17
    const int t  = gid & 15;
    const int b  = bc / CC;
    const int c  = bc % CC;
    const int a  = c % AA;                // negmask uses prob_gt[b, a]
    const int h0 = (t & 7) * HT;
    const int d0 = (t >> 3) * DCHUNK;

    const int  h     = h0 - 1 + ty;       // -1..128
    const bool hin   = (h >= 0) && (h < HH);
    const bool isout = (ty >= 1) && (ty <= HT);

    const float* chan = logits  + (size_t)(b * CC + c) * DD * HH * WW;
    const float* pga  = prob_gt + (size_t)(b * AA + a) * DD * HH * WW;
    const float* rowp = chan + (size_t)h * WW + lane * 4;   // valid iff hin
    const float* pgp  = pga  + (size_t)h * WW + lane * 4;   // valid iff isout

    const float4 ninf4 = make_float4(NEG_INF, NEG_INF, NEG_INF, NEG_INF);

    auto load_plane = [&](int pd) -> float4 {
        if (hin && pd >= 0 && pd < DD)
            return *(const float4*)(rowp + (size_t)pd * HH * WW);
        return ninf4;
    };
    auto hm3 = [&](int slot) -> float4 {
        return fmax4(fmax4(rbuf[slot][ty - 1][lane], rbuf[slot][ty][lane]),
                     rbuf[slot][ty + 1][lane]);
    };

    // ---- prologue: planes d0-1, d0, d0+1 published; L = planes d0+2, d0+3 ----
    float4 c0 = load_plane(d0);
    float4 c1 = load_plane(d0 + 1);
    {
        float4 vm1 = load_plane(d0 - 1);
        rbuf[(d0 - 1) & 3][ty][lane] = wmax3(vm1, lane);
        rbuf[(d0    ) & 3][ty][lane] = wmax3(c0, lane);
        rbuf[(d0 + 1) & 3][ty][lane] = wmax3(c1, lane);
    }
    float4 L0 = load_plane(d0 + 2);
    float4 L1 = load_plane(d0 + 3);
    __syncthreads();

    float4 hm_m1, hm_0, hm_p1;
    if (isout) {
        hm_m1 = hm3((d0 - 1) & 3);
        hm_0  = hm3((d0    ) & 3);
        hm_p1 = hm3((d0 + 1) & 3);
    }

    float loss = 0.0f, cnt = 0.0f;

    for (int d = d0; d < d0 + DCHUNK; d += 2) {
        // prob_gt for output planes d, d+1 (consumed after barrier)
        float4 pg0 = ninf4, pg1 = ninf4;
        if (isout) {
            pg0 = *(const float4*)(pgp + (size_t)d * HH * WW);
            pg1 = *(const float4*)(pgp + (size_t)(d + 1) * HH * WW);
        }

        // publish row-wmax of planes d+2, d+3 (loaded LAST iteration: no dep)
        rbuf[(d + 2) & 3][ty][lane] = wmax3(L0, lane);
        rbuf[(d + 3) & 3][ty][lane] = wmax3(L1, lane);

        // issue loads for planes d+4, d+5 (consumed NEXT iteration)
        float4 N0 = load_plane(d + 4);
        float4 N1 = load_plane(d + 5);

        __syncthreads();

        if (isout) {
            const float4 hm2 = hm3((d + 2) & 3);
            const float4 hmE = hm3((d + 3) & 3);

            const float4 m0 = fmax4(fmax4(hm_m1, hm_0), hm_p1);   // output d
            const float4 m1 = fmax4(fmax4(hm_0, hm_p1), hm2);     // output d+1

            const float mm0[4] = { m0.x, m0.y, m0.z, m0.w };
            const float cc0[4] = { c0.x, c0.y, c0.z, c0.w };
            const float pp0[4] = { pg0.x, pg0.y, pg0.z, pg0.w };
            const float mm1[4] = { m1.x, m1.y, m1.z, m1.w };
            const float cc1[4] = { c1.x, c1.y, c1.z, c1.w };
            const float pp1[4] = { pg1.x, pg1.y, pg1.z, pg1.w };
            #pragma unroll
            for (int i = 0; i < 4; ++i) {
                if (mm0[i] == cc0[i] && pp0[i] == -1.0f) {
                    float p = 1.0f / (1.0f + expf(-cc0[i]));
                    p = fminf(fmaxf(p, EPSF), 1.0f - EPSF);
                    if (p > EPSF) {
                        const float w = p * p;
                        loss -= logf(1.0f - p) * w;
                        cnt  += w;
                    }
                }
                if (mm1[i] == cc1[i] && pp1[i] == -1.0f) {
                    float p = 1.0f / (1.0f + expf(-cc1[i]));
                    p = fminf(fmaxf(p, EPSF), 1.0f - EPSF);
                    if (p > EPSF) {
                        const float w = p * p;
                        loss -= logf(1.0f - p) * w;
                        cnt  += w;
                    }
                }
            }
            // rotate hm window: next outputs d+2,d+3 need hm[d+1..d+4]
            hm_m1 = hm_p1;
            hm_0  = hm2;
            hm_p1 = hmE;
        }
        // rotate centers / load pipeline
        c0 = L0; c1 = L1;
        L0 = N0; L1 = N1;
    }

    // block reduction (18 warps; warp == one ty row)
    loss = warp_sum(loss);
    cnt  = warp_sum(cnt);
    if (lane == 0) { redl[ty] = loss; redc[ty] = cnt; }
    __syncthreads();
    if (tid == 0) {
        float l = 0.f, cv = 0.f;
        #pragma unroll
        for (int i = 0; i < NWARP; ++i) { l += redl[i]; cv += redc[i]; }
        atomicAdd(&out[1], l);    // loss_neg
        atomicAdd(&out[4], cv);   // count_neg
    }
}

extern "C" void kernel_launch(void* const* d_in, const int* in_sizes, int n_in,
                              void* d_out, int out_size)
{
    const float* logits  = (const float*)d_in[0];
    const float* prob_gt = (const float*)d_in[1];
    const int*   coord   = (const int*)d_in[2];
    const float* wcls    = (const float*)d_in[3];
    float* out = (float*)d_out;

    cudaMemsetAsync(out, 0, (size_t)out_size * sizeof(float));

    // 1D grid: 288 neg work blocks + 1 pos block
    focal_kernel<<<NEG_BLOCKS + 1, dim3(32, TYN)>>>(logits, prob_gt, coord, wcls, out);
}

// round 8
// speedup vs baseline: 1.1230x; 1.0342x over previous
#include <cuda_runtime.h>
#include <math.h>

// Problem constants
#define BB   2
#define AA   3
#define NCLS 3
#define CC   (NCLS*AA)   // 9 channels
#define DD   64
#define HH   128
#define WW   128
#define MM   128
#define EPSF 1e-4f

#define HT     8                 // h rows per block (one warp per row)
#define DSPLIT 2
#define DCHUNK (DD/DSPLIT)       // 32 d-slices per block
#define NWARP  HT                // 8 warps / block

#define HTILES (HH/HT)           // 16
#define NEG_BLOCKS (BB * CC * HTILES * DSPLIT)   // 576

#define NEG_INF __int_as_float(0xff800000)

__device__ __forceinline__ float warp_sum(float v) {
    #pragma unroll
    for (int o = 16; o; o >>= 1) v += __shfl_down_sync(0xffffffffu, v, o);
    return v;
}

__device__ __forceinline__ float4 fmax4(float4 a, float4 b) {
    return make_float4(fmaxf(a.x, b.x), fmaxf(a.y, b.y),
                       fmaxf(a.z, b.z), fmaxf(a.w, b.w));
}

// w-direction 3-window max of a row held as float4 per lane (warp-wide row).
__device__ __forceinline__ float4 wmax3(float4 v, int lane) {
    float left  = __shfl_up_sync(0xffffffffu, v.w, 1);
    float right = __shfl_down_sync(0xffffffffu, v.x, 1);
    if (lane == 0)  left  = NEG_INF;
    if (lane == 31) right = NEG_INF;
    float4 r;
    r.x = fmaxf(fmaxf(left, v.x), v.y);
    r.y = fmaxf(fmaxf(v.x, v.y), v.z);
    r.z = fmaxf(fmaxf(v.y, v.z), v.w);
    r.w = fmaxf(fmaxf(v.z, v.w), right);
    return r;
}

__global__ __launch_bounds__(32 * NWARP, 5)
void focal_kernel(const float* __restrict__ logits,
                  const float* __restrict__ prob_gt,
                  const int* __restrict__ coord,
                  const float* __restrict__ wcls,
                  float* __restrict__ out)
{
    const int lane = threadIdx.x;             // 0..31 (w4)
    const int ty   = threadIdx.y;             // 0..7 (h row within tile)
    const int tid  = ty * 32 + lane;
    const int gid  = blockIdx.x;

    // ======================= POS / OTHER path (one block) ===================
    if (gid == NEG_BLOCKS) {
        __shared__ int   present[BB][NCLS];
        __shared__ float rp0[NWARP], rp1[NWARP], rp2[NWARP], rp3[NWARP];

        if (tid < BB * NCLS) present[tid / NCLS][tid % NCLS] = 0;
        __syncthreads();

        const int b = tid >> 7;               // 256 threads = BB*MM exactly
        const int m = tid & (MM - 1);

        const int* cg = coord + ((size_t)b * MM + m) * 4;
        const int c0 = cg[0];
        const bool valid = c0 > -1;
        const int a = valid ? c0    : 0;
        const int d = valid ? cg[1] : 0;
        const int h = valid ? cg[2] : 0;
        const int w = valid ? cg[3] : 0;
        const float pgv = prob_gt[(((size_t)(b * AA + a) * DD + d) * HH + h) * WW + w];
        int cls = valid ? ((int)pgv - 1) : 0;
        cls = min(max(cls, 0), NCLS - 1);
        if (valid) present[b][cls] = 1;       // benign race
        __syncthreads();

        const float vf = valid ? 1.0f : 0.0f;
        auto getp = [&](int ch) -> float {
            const float x = logits[(((size_t)(b * CC + ch) * DD + d) * HH + h) * WW + w];
            float p = 1.0f / (1.0f + expf(-x));
            return fminf(fmaxf(p, EPSF), 1.0f - EPSF);
        };
        const float pt   = getp(cls * AA + a);
        const float omt  = 1.0f - pt;
        const float wpos = omt * omt * wcls[cls] * vf;
        float lpos = -logf(pt) * wpos;
        float cpos = wpos;

        float loth = 0.f, coth = 0.f;
        const float thr = pt - 0.1f;
        const float ptgate = (pt > 0.5f) ? 1.0f : 0.0f;
        #pragma unroll
        for (int k = 0; k < NCLS; ++k) {
            const float po = getp(k * AA + a);
            float wo = fmaxf(po - thr, 0.0f);
            wo *= (po > 0.5f) ? 1.0f : 0.0f;
            wo *= ptgate;
            if (present[b][k]) wo = 0.0f;
            wo *= vf;
            loth += -logf(1.0f - po) * wo;
            coth += wo;
        }

        const int wid = tid >> 5, ln = tid & 31;
        lpos = warp_sum(lpos); cpos = warp_sum(cpos);
        loth = warp_sum(loth); coth = warp_sum(coth);
        if (ln == 0) { rp0[wid] = lpos; rp1[wid] = cpos; rp2[wid] = loth; rp3[wid] = coth; }
        __syncthreads();
        if (tid == 0) {
            float s0 = 0, s1 = 0, s2 = 0, s3 = 0;
            #pragma unroll
            for (int i = 0; i < NWARP; ++i) { s0 += rp0[i]; s1 += rp1[i]; s2 += rp2[i]; s3 += rp3[i]; }
            atomicAdd(&out[0], s0);   // l_pos
            atomicAdd(&out[3], s1);   // c_pos
            atomicAdd(&out[2], s2);   // l_oth
            atomicAdd(&out[5], s3);   // c_oth
        }
        return;
    }

    // ============================ NEG path ==================================
    // gid in [0, 576): bc = gid/32; t = gid%32 -> h tile (16), d half (2)
    const int bc = gid >> 5;              // 0..17
    const int t  = gid & 31;
    const int b  = bc / CC;
    const int c  = bc % CC;
    const int a  = c % AA;                // negmask uses prob_gt[b, a]
    const int h0 = (t & 15) * HT;
    const int d0 = (t >> 4) * DCHUNK;

    const int h = h0 + ty;                // every warp produces output

    const float* chan = logits  + ((size_t)(b * CC + c) * DD * HH + h) * WW + lane * 4;
    const float* pgp  = prob_gt + ((size_t)(b * AA + a) * DD * HH + h) * WW + lane * 4;

    const bool topok = (h > 0);
    const bool botok = (h < HH - 1);

    const float4 ninf4 = make_float4(NEG_INF, NEG_INF, NEG_INF, NEG_INF);

    // vertical(3-row) max + center for plane pd
    auto load_vm = [&](int pd, float4& center) -> float4 {
        if (pd < 0 || pd >= DD) { center = ninf4; return ninf4; }
        const float* base = chan + (size_t)pd * HH * WW;
        float4 tm = topok ? *(const float4*)(base - WW) : ninf4;
        float4 mm = *(const float4*)(base);
        float4 bm = botok ? *(const float4*)(base + WW) : ninf4;
        center = mm;
        return fmax4(fmax4(tm, mm), bm);
    };
    auto load_pg = [&](int pd) -> float4 {
        if (pd >= DD) return ninf4;
        return *(const float4*)(pgp + (size_t)pd * HH * WW);
    };

    // ---- prologue ----
    float4 ccur, cdead;
    float4 whm_m1, whm_0;
    {
        float4 vm = load_vm(d0 - 1, cdead);
        whm_m1 = wmax3(vm, lane);
        vm = load_vm(d0, ccur);
        whm_0 = wmax3(vm, lane);
    }
    // preload plane d0+1 rows (raw) and pg(d0)
    float4 nt, nm, nb;
    {
        const float* base = chan + (size_t)(d0 + 1) * HH * WW;
        nt = topok ? *(const float4*)(base - WW) : ninf4;
        nm = *(const float4*)(base);
        nb = botok ? *(const float4*)(base + WW) : ninf4;
    }
    float4 pgc = load_pg(d0);

    float loss = 0.0f, cnt = 0.0f;

    for (int d = d0; d < d0 + DCHUNK; ++d) {
        // finish plane d+1: vertical+horizontal max from preloaded rows
        const float4 whm_p1 = wmax3(fmax4(fmax4(nt, nm), nb), lane);
        const float4 cnext  = nm;

        // issue loads for plane d+2 (consumed next iteration) and pg(d+1)
        {
            const int pd = d + 2;
            if (pd < DD) {
                const float* base = chan + (size_t)pd * HH * WW;
                nt = topok ? *(const float4*)(base - WW) : ninf4;
                nm = *(const float4*)(base);
                nb = botok ? *(const float4*)(base + WW) : ninf4;
            } else {
                nt = nm = nb = ninf4;
            }
        }
        float4 pgn = load_pg(d + 1);

        // 3x3x3 max for output plane d
        const float4 m = fmax4(fmax4(whm_m1, whm_0), whm_p1);

        {
            const float mm[4] = { m.x, m.y, m.z, m.w };
            const float cc[4] = { ccur.x, ccur.y, ccur.z, ccur.w };
            const float pp[4] = { pgc.x, pgc.y, pgc.z, pgc.w };
            #pragma unroll
            for (int i = 0; i < 4; ++i) {
                if (mm[i] == cc[i] && pp[i] == -1.0f) {
                    float p = 1.0f / (1.0f + expf(-cc[i]));
                    p = fminf(fmaxf(p, EPSF), 1.0f - EPSF);
                    if (p > EPSF) {
                        const float w = p * p;      // p^ALPHA, ALPHA=2
                        loss -= logf(1.0f - p) * w;
                        cnt  += w;
                    }
                }
            }
        }

        whm_m1 = whm_0;
        whm_0  = whm_p1;
        ccur   = cnext;
        pgc    = pgn;
    }

    // block reduction (8 warps)
    __shared__ float redl[NWARP], redc[NWARP];
    loss = warp_sum(loss);
    cnt  = warp_sum(cnt);
    if (lane == 0) { redl[ty] = loss; redc[ty] = cnt; }
    __syncthreads();
    if (tid == 0) {
        float l = 0.f, cv = 0.f;
        #pragma unroll
        for (int i = 0; i < NWARP; ++i) { l += redl[i]; cv += redc[i]; }
        atomicAdd(&out[1], l);    // loss_neg
        atomicAdd(&out[4], cv);   // count_neg
    }
}

extern "C" void kernel_launch(void* const* d_in, const int* in_sizes, int n_in,
                              void* d_out, int out_size)
{
    const float* logits  = (const float*)d_in[0];
    const float* prob_gt = (const float*)d_in[1];
    const int*   coord   = (const int*)d_in[2];
    const float* wcls    = (const float*)d_in[3];
    float* out = (float*)d_out;

    cudaMemsetAsync(out, 0, (size_t)out_size * sizeof(float));

    // 1D grid: 576 neg work blocks + 1 pos block; 256 threads each
    focal_kernel<<<NEG_BLOCKS + 1, dim3(32, NWARP)>>>(logits, prob_gt, coord, wcls, out);
}

// round 9
// speedup vs baseline: 1.2252x; 1.0910x over previous
#include <cuda_runtime.h>
#include <math.h>

// Problem constants
#define BB   2
#define AA   3
#define NCLS 3
#define CC   (NCLS*AA)   // 9 channels
#define DD   64
#define HH   128
#define WW   128
#define MM   128
#define EPSF 1e-4f

#define HT     8                 // h rows per block (one warp per row)
#define DSPLIT 4
#define DCHUNK (DD/DSPLIT)       // 16 d-slices per block
#define NWARP  HT                // 8 warps / block

#define HTILES (HH/HT)           // 16
#define NEG_BLOCKS (BB * CC * HTILES * DSPLIT)   // 1152

#define NEG_INF __int_as_float(0xff800000)

__device__ __forceinline__ float warp_sum(float v) {
    #pragma unroll
    for (int o = 16; o; o >>= 1) v += __shfl_down_sync(0xffffffffu, v, o);
    return v;
}

__device__ __forceinline__ float4 fmax4(float4 a, float4 b) {
    return make_float4(fmaxf(a.x, b.x), fmaxf(a.y, b.y),
                       fmaxf(a.z, b.z), fmaxf(a.w, b.w));
}

// w-direction 3-window max of a row held as float4 per lane (warp-wide row).
__device__ __forceinline__ float4 wmax3(float4 v, int lane) {
    float left  = __shfl_up_sync(0xffffffffu, v.w, 1);
    float right = __shfl_down_sync(0xffffffffu, v.x, 1);
    if (lane == 0)  left  = NEG_INF;
    if (lane == 31) right = NEG_INF;
    float4 r;
    r.x = fmaxf(fmaxf(left, v.x), v.y);
    r.y = fmaxf(fmaxf(v.x, v.y), v.z);
    r.z = fmaxf(fmaxf(v.y, v.z), v.w);
    r.w = fmaxf(fmaxf(v.z, v.w), right);
    return r;
}

__global__ __launch_bounds__(32 * NWARP, 5)
void focal_kernel(const float* __restrict__ logits,
                  const float* __restrict__ prob_gt,
                  const int* __restrict__ coord,
                  const float* __restrict__ wcls,
                  float* __restrict__ out)
{
    const int lane = threadIdx.x;             // 0..31 (w4)
    const int ty   = threadIdx.y;             // 0..7 (h row within tile)
    const int tid  = ty * 32 + lane;
    const int gid  = blockIdx.x;

    // ======================= POS / OTHER path (one block) ===================
    if (gid == NEG_BLOCKS) {
        __shared__ int   present[BB][NCLS];
        __shared__ float rp0[NWARP], rp1[NWARP], rp2[NWARP], rp3[NWARP];

        if (tid < BB * NCLS) present[tid / NCLS][tid % NCLS] = 0;
        __syncthreads();

        const int b = tid >> 7;               // 256 threads = BB*MM exactly
        const int m = tid & (MM - 1);

        const int* cg = coord + ((size_t)b * MM + m) * 4;
        const int c0 = cg[0];
        const bool valid = c0 > -1;
        const int a = valid ? c0    : 0;
        const int d = valid ? cg[1] : 0;
        const int h = valid ? cg[2] : 0;
        const int w = valid ? cg[3] : 0;
        const float pgv = prob_gt[(((size_t)(b * AA + a) * DD + d) * HH + h) * WW + w];
        int cls = valid ? ((int)pgv - 1) : 0;
        cls = min(max(cls, 0), NCLS - 1);
        if (valid) present[b][cls] = 1;       // benign race
        __syncthreads();

        const float vf = valid ? 1.0f : 0.0f;
        auto getp = [&](int ch) -> float {
            const float x = logits[(((size_t)(b * CC + ch) * DD + d) * HH + h) * WW + w];
            float p = 1.0f / (1.0f + expf(-x));
            return fminf(fmaxf(p, EPSF), 1.0f - EPSF);
        };
        const float pt   = getp(cls * AA + a);
        const float omt  = 1.0f - pt;
        const float wpos = omt * omt * wcls[cls] * vf;
        float lpos = -logf(pt) * wpos;
        float cpos = wpos;

        float loth = 0.f, coth = 0.f;
        const float thr = pt - 0.1f;
        const float ptgate = (pt > 0.5f) ? 1.0f : 0.0f;
        #pragma unroll
        for (int k = 0; k < NCLS; ++k) {
            const float po = getp(k * AA + a);
            float wo = fmaxf(po - thr, 0.0f);
            wo *= (po > 0.5f) ? 1.0f : 0.0f;
            wo *= ptgate;
            if (present[b][k]) wo = 0.0f;
            wo *= vf;
            loth += -logf(1.0f - po) * wo;
            coth += wo;
        }

        const int wid = tid >> 5, ln = tid & 31;
        lpos = warp_sum(lpos); cpos = warp_sum(cpos);
        loth = warp_sum(loth); coth = warp_sum(coth);
        if (ln == 0) { rp0[wid] = lpos; rp1[wid] = cpos; rp2[wid] = loth; rp3[wid] = coth; }
        __syncthreads();
        if (tid == 0) {
            float s0 = 0, s1 = 0, s2 = 0, s3 = 0;
            #pragma unroll
            for (int i = 0; i < NWARP; ++i) { s0 += rp0[i]; s1 += rp1[i]; s2 += rp2[i]; s3 += rp3[i]; }
            atomicAdd(&out[0], s0);   // l_pos
            atomicAdd(&out[3], s1);   // c_pos
            atomicAdd(&out[2], s2);   // l_oth
            atomicAdd(&out[5], s3);   // c_oth
        }
        return;
    }

    // ============================ NEG path ==================================
    // gid in [0, 1152): bc = gid/64; t = gid%64 -> h tile (16) x d quarter (4)
    const int bc = gid >> 6;              // 0..17
    const int t  = gid & 63;
    const int b  = bc / CC;
    const int c  = bc % CC;
    const int a  = c % AA;                // negmask uses prob_gt[b, a]
    const int h0 = (t & 15) * HT;
    const int d0 = (t >> 4) * DCHUNK;

    const int h = h0 + ty;                // every warp produces output

    const float* chan = logits  + ((size_t)(b * CC + c) * DD * HH + h) * WW + lane * 4;
    const float* pgp  = prob_gt + ((size_t)(b * AA + a) * DD * HH + h) * WW + lane * 4;

    const bool topok = (h > 0);
    const bool botok = (h < HH - 1);

    const float4 ninf4 = make_float4(NEG_INF, NEG_INF, NEG_INF, NEG_INF);

    // vertical(3-row) max + center for plane pd
    auto load_vm = [&](int pd, float4& center) -> float4 {
        if (pd < 0 || pd >= DD) { center = ninf4; return ninf4; }
        const float* base = chan + (size_t)pd * HH * WW;
        float4 tm = topok ? *(const float4*)(base - WW) : ninf4;
        float4 mm = *(const float4*)(base);
        float4 bm = botok ? *(const float4*)(base + WW) : ninf4;
        center = mm;
        return fmax4(fmax4(tm, mm), bm);
    };
    auto load_pg = [&](int pd) -> float4 {
        if (pd >= DD) return ninf4;
        return *(const float4*)(pgp + (size_t)pd * HH * WW);
    };

    // ---- prologue ----
    float4 ccur, cdead;
    float4 whm_m1, whm_0;
    {
        float4 vm = load_vm(d0 - 1, cdead);
        whm_m1 = wmax3(vm, lane);
        vm = load_vm(d0, ccur);
        whm_0 = wmax3(vm, lane);
    }
    // preload plane d0+1 rows (raw) and pg(d0)
    float4 nt, nm, nb;
    {
        const float* base = chan + (size_t)(d0 + 1) * HH * WW;
        nt = topok ? *(const float4*)(base - WW) : ninf4;
        nm = *(const float4*)(base);
        nb = botok ? *(const float4*)(base + WW) : ninf4;
    }
    float4 pgc = load_pg(d0);

    float loss = 0.0f, cnt = 0.0f;

    for (int d = d0; d < d0 + DCHUNK; ++d) {
        // finish plane d+1: vertical+horizontal max from preloaded rows
        const float4 whm_p1 = wmax3(fmax4(fmax4(nt, nm), nb), lane);
        const float4 cnext  = nm;

        // issue loads for plane d+2 (consumed next iteration) and pg(d+1)
        {
            const int pd = d + 2;
            if (pd < DD) {
                const float* base = chan + (size_t)pd * HH * WW;
                nt = topok ? *(const float4*)(base - WW) : ninf4;
                nm = *(const float4*)(base);
                nb = botok ? *(const float4*)(base + WW) : ninf4;
            } else {
                nt = nm = nb = ninf4;
            }
        }
        float4 pgn = load_pg(d + 1);

        // 3x3x3 max for output plane d
        const float4 m = fmax4(fmax4(whm_m1, whm_0), whm_p1);

        {
            const bool b0 = (m.x == ccur.x) && (pgc.x == -1.0f);
            const bool b1 = (m.y == ccur.y) && (pgc.y == -1.0f);
            const bool b2 = (m.z == ccur.z) && (pgc.z == -1.0f);
            const bool b3 = (m.w == ccur.w) && (pgc.w == -1.0f);
            if (b0 | b1 | b2 | b3) {
                const bool  bb[4] = { b0, b1, b2, b3 };
                const float cc[4] = { ccur.x, ccur.y, ccur.z, ccur.w };
                #pragma unroll
                for (int i = 0; i < 4; ++i) {
                    if (bb[i]) {
                        float p = 1.0f / (1.0f + expf(-cc[i]));
                        p = fminf(fmaxf(p, EPSF), 1.0f - EPSF);
                        if (p > EPSF) {
                            const float w = p * p;      // p^ALPHA, ALPHA=2
                            loss -= logf(1.0f - p) * w;
                            cnt  += w;
                        }
                    }
                }
            }
        }

        whm_m1 = whm_0;
        whm_0  = whm_p1;
        ccur   = cnext;
        pgc    = pgn;
    }

    // block reduction (8 warps)
    __shared__ float redl[NWARP], redc[NWARP];
    loss = warp_sum(loss);
    cnt  = warp_sum(cnt);
    if (lane == 0) { redl[ty] = loss; redc[ty] = cnt; }
    __syncthreads();
    if (tid == 0) {
        float l = 0.f, cv = 0.f;
        #pragma unroll
        for (int i = 0; i < NWARP; ++i) { l += redl[i]; cv += redc[i]; }
        atomicAdd(&out[1], l);    // loss_neg
        atomicAdd(&out[4], cv);   // count_neg
    }
}

extern "C" void kernel_launch(void* const* d_in, const int* in_sizes, int n_in,
                              void* d_out, int out_size)
{
    const float* logits  = (const float*)d_in[0];
    const float* prob_gt = (const float*)d_in[1];
    const int*   coord   = (const int*)d_in[2];
    const float* wcls    = (const float*)d_in[3];
    float* out = (float*)d_out;

    cudaMemsetAsync(out, 0, (size_t)out_size * sizeof(float));

    // 1D grid: 1152 neg work blocks + 1 pos block; 256 threads each
    focal_kernel<<<NEG_BLOCKS + 1, dim3(32, NWARP)>>>(logits, prob_gt, coord, wcls, out);
}

// round 10
// speedup vs baseline: 1.2917x; 1.0542x over previous
#include <cuda_runtime.h>
#include <math.h>

// Problem constants
#define BB   2
#define AA   3
#define NCLS 3
#define CC   (NCLS*AA)   // 9 channels
#define DD   64
#define HH   128
#define WW   128
#define MM   128
#define EPSF 1e-4f

#define HT     8                 // h rows per block (one warp per row)
#define DSPLIT 4
#define DCHUNK (DD/DSPLIT)       // 16 d-slices per block
#define NWARP  HT                // 8 warps / block
#define HHWW   (HH*WW)

#define HTILES (HH/HT)           // 16
#define NEG_BLOCKS (BB * CC * HTILES * DSPLIT)   // 1152

#define NEG_INF __int_as_float(0xff800000)

__device__ __forceinline__ float warp_sum(float v) {
    #pragma unroll
    for (int o = 16; o; o >>= 1) v += __shfl_down_sync(0xffffffffu, v, o);
    return v;
}

__device__ __forceinline__ float4 fmax4(float4 a, float4 b) {
    return make_float4(fmaxf(a.x, b.x), fmaxf(a.y, b.y),
                       fmaxf(a.z, b.z), fmaxf(a.w, b.w));
}

// w-direction 3-window max of a row held as float4 per lane (warp-wide row).
__device__ __forceinline__ float4 wmax3(float4 v, int lane) {
    float left  = __shfl_up_sync(0xffffffffu, v.w, 1);
    float right = __shfl_down_sync(0xffffffffu, v.x, 1);
    if (lane == 0)  left  = NEG_INF;
    if (lane == 31) right = NEG_INF;
    float4 r;
    r.x = fmaxf(fmaxf(left, v.x), v.y);
    r.y = fmaxf(fmaxf(v.x, v.y), v.z);
    r.z = fmaxf(fmaxf(v.y, v.z), v.w);
    r.w = fmaxf(fmaxf(v.z, v.w), right);
    return r;
}

__global__ __launch_bounds__(32 * NWARP, 5)
void focal_kernel(const float* __restrict__ logits,
                  const float* __restrict__ prob_gt,
                  const int* __restrict__ coord,
                  const float* __restrict__ wcls,
                  float* __restrict__ out)
{
    const int lane = threadIdx.x;             // 0..31 (w4)
    const int ty   = threadIdx.y;             // 0..7 (h row within tile)
    const int tid  = ty * 32 + lane;
    const int gid  = blockIdx.x;

    // ======================= POS / OTHER path (one block) ===================
    if (gid == NEG_BLOCKS) {
        __shared__ int   present[BB][NCLS];
        __shared__ float rp0[NWARP], rp1[NWARP], rp2[NWARP], rp3[NWARP];

        if (tid < BB * NCLS) present[tid / NCLS][tid % NCLS] = 0;
        __syncthreads();

        const int b = tid >> 7;               // 256 threads = BB*MM exactly
        const int m = tid & (MM - 1);

        const int* cg = coord + ((size_t)b * MM + m) * 4;
        const int c0 = cg[0];
        const bool valid = c0 > -1;
        const int a = valid ? c0    : 0;
        const int d = valid ? cg[1] : 0;
        const int h = valid ? cg[2] : 0;
        const int w = valid ? cg[3] : 0;
        const float pgv = prob_gt[(((size_t)(b * AA + a) * DD + d) * HH + h) * WW + w];
        int cls = valid ? ((int)pgv - 1) : 0;
        cls = min(max(cls, 0), NCLS - 1);
        if (valid) present[b][cls] = 1;       // benign race
        __syncthreads();

        const float vf = valid ? 1.0f : 0.0f;
        auto getp = [&](int ch) -> float {
            const float x = logits[(((size_t)(b * CC + ch) * DD + d) * HH + h) * WW + w];
            float p = 1.0f / (1.0f + expf(-x));
            return fminf(fmaxf(p, EPSF), 1.0f - EPSF);
        };
        const float pt   = getp(cls * AA + a);
        const float omt  = 1.0f - pt;
        const float wpos = omt * omt * wcls[cls] * vf;
        float lpos = -logf(pt) * wpos;
        float cpos = wpos;

        float loth = 0.f, coth = 0.f;
        const float thr = pt - 0.1f;
        const float ptgate = (pt > 0.5f) ? 1.0f : 0.0f;
        #pragma unroll
        for (int k = 0; k < NCLS; ++k) {
            const float po = getp(k * AA + a);
            float wo = fmaxf(po - thr, 0.0f);
            wo *= (po > 0.5f) ? 1.0f : 0.0f;
            wo *= ptgate;
            if (present[b][k]) wo = 0.0f;
            wo *= vf;
            loth += -logf(1.0f - po) * wo;
            coth += wo;
        }

        const int wid = tid >> 5, ln = tid & 31;
        lpos = warp_sum(lpos); cpos = warp_sum(cpos);
        loth = warp_sum(loth); coth = warp_sum(coth);
        if (ln == 0) { rp0[wid] = lpos; rp1[wid] = cpos; rp2[wid] = loth; rp3[wid] = coth; }
        __syncthreads();
        if (tid == 0) {
            float s0 = 0, s1 = 0, s2 = 0, s3 = 0;
            #pragma unroll
            for (int i = 0; i < NWARP; ++i) { s0 += rp0[i]; s1 += rp1[i]; s2 += rp2[i]; s3 += rp3[i]; }
            atomicAdd(&out[0], s0);   // l_pos
            atomicAdd(&out[3], s1);   // c_pos
            atomicAdd(&out[2], s2);   // l_oth
            atomicAdd(&out[5], s3);   // c_oth
        }
        return;
    }

    // ============================ NEG path ==================================
    // gid in [0, 1152): bc = gid/64; t = gid%64 -> h tile (16) x d quarter (4)
    const int bc = gid >> 6;              // 0..17
    const int t  = gid & 63;
    const int b  = bc / CC;
    const int c  = bc % CC;
    const int a  = c % AA;                // negmask uses prob_gt[b, a]
    const int h0 = (t & 15) * HT;
    const int d0 = (t >> 4) * DCHUNK;

    const int h = h0 + ty;                // every warp produces output

    const float* chan = logits  + ((size_t)(b * CC + c) * DD * HH + h) * WW + lane * 4;
    const float* pgp  = prob_gt + ((size_t)(b * AA + a) * DD * HH + h) * WW + lane * 4;

    // 'SAME'-pool boundary clamp: duplicated edge row/plane == clipped window
    const int topoff = (h > 0)      ? -WW : 0;
    const int botoff = (h < HH - 1) ?  WW : 0;

    // ---- prologue ----
    float4 whm_m1, whm_0, ccur;
    {
        const float* base = chan + (size_t)max(d0 - 1, 0) * HHWW;
        float4 vm = fmax4(fmax4(*(const float4*)(base + topoff),
                                *(const float4*)(base)),
                          *(const float4*)(base + botoff));
        whm_m1 = wmax3(vm, lane);
        base = chan + (size_t)d0 * HHWW;
        float4 mm = *(const float4*)(base);
        ccur = mm;
        vm = fmax4(fmax4(*(const float4*)(base + topoff), mm),
                   *(const float4*)(base + botoff));
        whm_0 = wmax3(vm, lane);
    }
    // preload plane d0+1 rows (raw) and pg(d0)
    float4 nt, nm, nb;
    {
        const float* base = chan + (size_t)(d0 + 1) * HHWW;
        nt = *(const float4*)(base + topoff);
        nm = *(const float4*)(base);
        nb = *(const float4*)(base + botoff);
    }
    float4 pgc = *(const float4*)(pgp + (size_t)d0 * HHWW);

    float loss = 0.0f, cnt = 0.0f;

    #pragma unroll 4
    for (int d = d0; d < d0 + DCHUNK; ++d) {
        // finish plane d+1: vertical+horizontal max from preloaded rows
        const float4 whm_p1 = wmax3(fmax4(fmax4(nt, nm), nb), lane);
        const float4 cnext  = nm;

        // issue loads for plane d+2 (clamped at volume edge) and pg(d+1)
        {
            const float* base = chan + (size_t)min(d + 2, DD - 1) * HHWW;
            nt = *(const float4*)(base + topoff);
            nm = *(const float4*)(base);
            nb = *(const float4*)(base + botoff);
        }
        const float4 pgn = *(const float4*)(pgp + (size_t)min(d + 1, DD - 1) * HHWW);

        // 3x3x3 max for output plane d
        const float4 m = fmax4(fmax4(whm_m1, whm_0), whm_p1);

        {
            const bool b0 = (m.x == ccur.x) && (pgc.x == -1.0f);
            const bool b1 = (m.y == ccur.y) && (pgc.y == -1.0f);
            const bool b2 = (m.z == ccur.z) && (pgc.z == -1.0f);
            const bool b3 = (m.w == ccur.w) && (pgc.w == -1.0f);
            if (b0 | b1 | b2 | b3) {
                const bool  bb[4] = { b0, b1, b2, b3 };
                const float cc[4] = { ccur.x, ccur.y, ccur.z, ccur.w };
                #pragma unroll
                for (int i = 0; i < 4; ++i) {
                    if (bb[i]) {
                        float p = __fdividef(1.0f, 1.0f + __expf(-cc[i]));
                        p = fminf(fmaxf(p, EPSF), 1.0f - EPSF);
                        if (p > EPSF) {
                            const float w = p * p;      // p^ALPHA, ALPHA=2
                            loss -= __logf(1.0f - p) * w;
                            cnt  += w;
                        }
                    }
                }
            }
        }

        whm_m1 = whm_0;
        whm_0  = whm_p1;
        ccur   = cnext;
        pgc    = pgn;
    }

    // block reduction (8 warps)
    __shared__ float redl[NWARP], redc[NWARP];
    loss = warp_sum(loss);
    cnt  = warp_sum(cnt);
    if (lane == 0) { redl[ty] = loss; redc[ty] = cnt; }
    __syncthreads();
    if (tid == 0) {
        float l = 0.f, cv = 0.f;
        #pragma unroll
        for (int i = 0; i < NWARP; ++i) { l += redl[i]; cv += redc[i]; }
        atomicAdd(&out[1], l);    // loss_neg
        atomicAdd(&out[4], cv);   // count_neg
    }
}

extern "C" void kernel_launch(void* const* d_in, const int* in_sizes, int n_in,
                              void* d_out, int out_size)
{
    const float* logits  = (const float*)d_in[0];
    const float* prob_gt = (const float*)d_in[1];
    const int*   coord   = (const int*)d_in[2];
    const float* wcls    = (const float*)d_in[3];
    float* out = (float*)d_out;

    cudaMemsetAsync(out, 0, (size_t)out_size * sizeof(float));

    // 1D grid: 1152 neg work blocks + 1 pos block; 256 threads each
    focal_kernel<<<NEG_BLOCKS + 1, dim3(32, NWARP)>>>(logits, prob_gt, coord, wcls, out);
}